// round 15
// baseline (speedup 1.0000x reference)
#include <cuda_runtime.h>
#include <cuda_fp16.h>
#include <cstdint>

// ===========================================================================
// CFConv via mma.sync (HMMA fp16 m16n8k16, fp32 accum), single-pass fp16.
// 256 thr / CTA = 8 warps = 4 atom-PAIRS (2 warps per atom, N=64 per warp).
// R15: (1) softplus computed in half2 (h2exp/h2log) -> half the MUFU ops,
//      numerically consistent with fp16 H storage. (2) epilogue x-gather
//      reads a prep-built fp16 image of x (half the gather bytes).
// Reg-forwarded own-half A2 frags; shuffle-reduce epilogue; 2 bars/tile.
// ===========================================================================

#define N_THREADS 256
#define ATOMS_PER_CTA 8
#define F_DIM 128

// padded element strides (odd multiples of 8 halves -> conflict-free ldmatrix)
#define S1 72    // K=64 tiles
#define S2 136   // K=128 tiles

// ---- smem byte offsets ----
#define SM_B1H 0                         // 128*72*2  = 18432
#define SM_B2H (SM_B1H + 128*S1*2)       // 128*136*2 = 34816 -> ends 53248
#define SM_A1H (SM_B2H + 128*S2*2)       // 128*72*2  = 18432 -> ends 71680
#define SM_HH  (SM_A1H + 128*S1*2)       // 128*136*2 = 34816 -> ends 106496
#define SM_BS1 (SM_HH  + 128*S2*2)       // 512
#define SM_BS2 (SM_BS1 + 512)
#define SMEM_BYTES (SM_BS2 + 512)        // 107520 (2 CTAs: 215040 <= 227328)

#define WIMG_BYTES (128*S1*2 + 128*S2*2) // 53248
#define X_CAP (20480 * F_DIM)            // fp16 x image capacity (elems)
__device__ __align__(16) unsigned char g_wimg[WIMG_BYTES];
__device__ __align__(16) __half g_ximg[X_CAP];   // 5.24 MB
__device__ int g_idx64_flag;

// ---------------------------------------------------------------------------
__device__ __forceinline__ uint32_t smem_u32(const void* p) {
    uint32_t a;
    asm("{ .reg .u64 t; cvta.to.shared.u64 t, %1; cvt.u32.u64 %0, t; }" : "=r"(a) : "l"(p));
    return a;
}
__device__ __forceinline__ void bar_pair(int id) {
    asm volatile("bar.sync %0, %1;" :: "r"(id), "r"(64) : "memory");
}
__device__ __forceinline__ void ldsm4(uint32_t addr, uint32_t r[4]) {
    asm volatile("ldmatrix.sync.aligned.m8n8.x4.shared.b16 {%0,%1,%2,%3}, [%4];"
        : "=r"(r[0]), "=r"(r[1]), "=r"(r[2]), "=r"(r[3]) : "r"(addr));
}
__device__ __forceinline__ void mma16816(float c[4], const uint32_t a[4],
                                         uint32_t b0, uint32_t b1) {
    asm volatile("mma.sync.aligned.m16n8k16.row.col.f32.f16.f16.f32 "
        "{%0,%1,%2,%3}, {%4,%5,%6,%7}, {%8,%9}, {%0,%1,%2,%3};"
        : "+f"(c[0]), "+f"(c[1]), "+f"(c[2]), "+f"(c[3])
        : "r"(a[0]), "r"(a[1]), "r"(a[2]), "r"(a[3]), "r"(b0), "r"(b1));
}
__device__ __forceinline__ uint32_t pack_h2(float a, float b) {
    __half2 h = __floats2half2_rn(a, b);
    return *reinterpret_cast<uint32_t*>(&h);
}
// softplus on a packed half2: max(z,0) + log(1 + exp(-|z|))
__device__ __forceinline__ uint32_t softplus_h2(uint32_t zbits) {
    __half2 z = *reinterpret_cast<__half2*>(&zbits);
    const __half2 zero = __float2half2_rn(0.0f);
    const __half2 one  = __float2half2_rn(1.0f);
    __half2 e = h2exp(__hneg2(__habs2(z)));
    __half2 l = h2log(__hadd2(one, e));
    __half2 r = __hadd2(__hmax2(z, zero), l);
    return *reinterpret_cast<uint32_t*>(&r);
}

// A: [128 rows][STRIDE k] fp16; B: [128 n][STRIDE k] fp16. Single pass.
template<int KSTEPS, int STRIDE>
__device__ __forceinline__ void gemm_block(
    uint32_t aH, uint32_t bH,
    int m0, int nb0, int lane, float c[2][8][4])
{
    const uint32_t a_row = m0 + (lane & 15);
    const uint32_t a_k   = (lane >> 4) << 3;
    const uint32_t b_row = nb0 + ((lane >> 4) << 3) + (lane & 7);
    const uint32_t b_k   = ((lane >> 3) & 1) << 3;
    #pragma unroll
    for (int ks = 0; ks < KSTEPS; ++ks) {
        const uint32_t k0 = ks * 16;
        uint32_t ah[2][4];
        #pragma unroll
        for (int mi = 0; mi < 2; ++mi) {
            uint32_t off = ((a_row + mi * 16) * STRIDE + k0 + a_k) * 2;
            ldsm4(aH + off, ah[mi]);
        }
        #pragma unroll
        for (int ng = 0; ng < 4; ++ng) {
            uint32_t boff = ((b_row + ng * 16) * STRIDE + k0 + b_k) * 2;
            uint32_t bh[4];
            ldsm4(bH + boff, bh);
            #pragma unroll
            for (int mi = 0; mi < 2; ++mi)
                #pragma unroll
                for (int nj = 0; nj < 2; ++nj)
                    mma16816(c[mi][ng * 2 + nj], ah[mi], bh[2*nj], bh[2*nj+1]);
        }
    }
}

// stage one atom's rbf rows [32 x 64] -> fp16 into A (pair-cooperative, 64 thr)
__device__ __forceinline__ void stage_A(char* smem, const float* __restrict__ rbf,
                                        int atom, bool ok, int m0, int pt)
{
    const float4* rg = (const float4*)rbf + (size_t)atom * 512;
    #pragma unroll
    for (int i = 0; i < 8; ++i) {
        int idx = pt + i * 64;                 // 0..511
        int row = idx >> 4, c4 = (idx & 15) << 2;
        float4 v = make_float4(0.f, 0.f, 0.f, 0.f);
        if (ok) v = rg[idx];
        uint32_t o = (uint32_t)((m0 + row) * S1 + c4) * 2;
        *(uint2*)(smem + SM_A1H + o) =
            make_uint2(pack_h2(v.x, v.y), pack_h2(v.z, v.w));
    }
}

// ---------------------------------------------------------------------------
// prep: weight transpose + fp16 images + fp16 x image; block 0 detects dtype
// ---------------------------------------------------------------------------
__global__ void prep_weights(const float* __restrict__ w1,
                             const float* __restrict__ w2,
                             const float* __restrict__ x,
                             int n_x,
                             const int*   __restrict__ nb_raw) {
    if (blockIdx.x == 0) {
        __shared__ int nonzero;
        if (threadIdx.x == 0) nonzero = 0;
        __syncthreads();
        int local = 0;
        for (int i = threadIdx.x; i < 1024; i += blockDim.x) local |= nb_raw[2 * i + 1];
        if (local) atomicOr(&nonzero, 1);
        __syncthreads();
        if (threadIdx.x == 0) g_idx64_flag = (nonzero == 0) ? 1 : 0;
    }
    uint16_t* b1h = (uint16_t*)(g_wimg);
    uint16_t* b2h = (uint16_t*)(g_wimg + 128*S1*2);
    int stride = gridDim.x * blockDim.x;
    int g0 = blockIdx.x * blockDim.x + threadIdx.x;
    for (int idx = g0; idx < 64*128; idx += stride) {
        int r = idx >> 7, f = idx & 127;
        b1h[f * S1 + r] = __half_as_ushort(__float2half_rn(w1[idx]));
    }
    for (int idx = g0; idx < 128*128; idx += stride) {
        int g = idx >> 7, f = idx & 127;
        b2h[f * S2 + g] = __half_as_ushort(__float2half_rn(w2[idx]));
    }
    // fp16 x image (vectorized: 4 floats -> 2 half2 per iteration)
    const int n4 = n_x >> 2;
    const float4* x4 = (const float4*)x;
    uint2* xi = (uint2*)g_ximg;
    for (int idx = g0; idx < n4; idx += stride) {
        if (idx * 4 + 3 < X_CAP) {
            float4 v = x4[idx];
            xi[idx] = make_uint2(pack_h2(v.x, v.y), pack_h2(v.z, v.w));
        }
    }
}

// ---------------------------------------------------------------------------
__global__ __launch_bounds__(N_THREADS, 2)
void cfconv_mma(const float* __restrict__ x,
                const float* __restrict__ rbf,
                const void*  __restrict__ nbr,
                const float* __restrict__ b1,
                const float* __restrict__ b2,
                float* __restrict__ out,
                int n_atoms)
{
    extern __shared__ __align__(16) char smem[];
    const uint32_t sb = smem_u32(smem);
    const int t = threadIdx.x, wid = t >> 5, lane = t & 31;

    // weights image -> smem: 53248 B = 3328 float4 = 13 x 256
    {
        const float4* src = (const float4*)g_wimg;
        float4* dst = (float4*)smem;
        #pragma unroll
        for (int i = 0; i < 13; ++i) dst[t + i * N_THREADS] = src[t + i * N_THREADS];
    }
    if (t < F_DIM) {
        ((float*)(smem + SM_BS1))[t] = b1[t];
        ((float*)(smem + SM_BS2))[t] = b2[t];
    }

    const int idxsh = g_idx64_flag;
    const int* nb32 = (const int*)nbr;
    const float* bs1 = (const float*)(smem + SM_BS1);
    const float* bs2 = (const float*)(smem + SM_BS2);

    // pair = consecutive warps {2p, 2p+1}; 4 pairs cover all SMSPs.
    const int pr  = wid >> 1;           // atom slot within tile (0..3)
    const int sub = wid & 1;            // N-half (0..1)
    const int bid = pr + 1;             // named barrier id (1..4), 64 thr
    const int m0  = pr * 32;
    const int nb0 = sub * 64;
    const int pt  = sub * 32 + lane;    // thread index within pair (0..63)
    const int qr  = lane >> 2;
    const int qc  = (lane & 3) * 2;

    __syncthreads();   // weights/biases ready (only CTA-wide sync)

    // ---- prologue: stage tile 0's A rows ----
    {
        const int atom0 = blockIdx.x * ATOMS_PER_CTA + pr;
        stage_A(smem, rbf, atom0, atom0 < n_atoms, m0, pt);
    }
    bar_pair(bid);       // A(0) ready

    #pragma unroll 1
    for (int tile = 0; tile < ATOMS_PER_CTA / 4; ++tile) {
        const int abase = blockIdx.x * ATOMS_PER_CTA + tile * 4;
        const int atom  = abase + pr;
        const bool ok   = (atom < n_atoms);

        float c[2][8][4];
        #pragma unroll
        for (int mi = 0; mi < 2; ++mi)
            #pragma unroll
            for (int ng = 0; ng < 8; ++ng)
                c[mi][ng][0] = c[mi][ng][1] = c[mi][ng][2] = c[mi][ng][3] = 0.f;

        // ---- GEMM1: A@B1 (fp16) ----
        gemm_block<4, S1>(sb + SM_A1H, sb + SM_B1H, m0, nb0, lane, c);

        // ---- softplus(D1+b1) in half2 -> regs (A2 own-half frags) + smem ----
        uint32_t hA[2][8], hB[2][8];   // row qr / row qr+8 packs
        #pragma unroll
        for (int mi = 0; mi < 2; ++mi) {
            #pragma unroll
            for (int ng = 0; ng < 8; ++ng) {
                const int cc = nb0 + ng * 8 + qc;
                const int r0 = m0 + mi * 16 + qr;
                const float bx = bs1[cc], by = bs1[cc + 1];
                hA[mi][ng] = softplus_h2(pack_h2(c[mi][ng][0] + bx,
                                                 c[mi][ng][1] + by));
                hB[mi][ng] = softplus_h2(pack_h2(c[mi][ng][2] + bx,
                                                 c[mi][ng][3] + by));
                *(uint32_t*)(smem + SM_HH + (uint32_t)(r0 * S2 + cc) * 2)
                    = hA[mi][ng];
                *(uint32_t*)(smem + SM_HH + (uint32_t)((r0 + 8) * S2 + cc) * 2)
                    = hB[mi][ng];
            }
        }
        bar_pair(bid);   // #1: H halves ready; A consumed by pair's GEMM1

        // ---- stage NEXT tile's A under GEMM2 latency ----
        if (tile + 1 < ATOMS_PER_CTA / 4) {
            const int natom = abase + 4 + pr;
            stage_A(smem, rbf, natom, natom < n_atoms, m0, pt);
        }

        // neighbor indices for this atom (overlaps GEMM2 latency)
        int j = 0;
        if (ok) j = nb32[((size_t)atom * 32 + lane) << idxsh];

        #pragma unroll
        for (int mi = 0; mi < 2; ++mi)
            #pragma unroll
            for (int ng = 0; ng < 8; ++ng)
                c[mi][ng][0] = c[mi][ng][1] = c[mi][ng][2] = c[mi][ng][3] = 0.f;

        // ---- GEMM2: H@B2 (fp16). Own 4 k-tiles from regs, partner 4 via ldsm.
        {
            const uint32_t b_row = nb0 + ((lane >> 4) << 3) + (lane & 7);
            const uint32_t b_k   = ((lane >> 3) & 1) << 3;
            // own-half k-tiles (k cols nb0..nb0+63): A frags = softplus packs
            #pragma unroll
            for (int kl = 0; kl < 4; ++kl) {
                uint32_t ah0[4] = { hA[0][2*kl], hB[0][2*kl],
                                    hA[0][2*kl+1], hB[0][2*kl+1] };
                uint32_t ah1[4] = { hA[1][2*kl], hB[1][2*kl],
                                    hA[1][2*kl+1], hB[1][2*kl+1] };
                const uint32_t k0 = nb0 + kl * 16;
                #pragma unroll
                for (int ng = 0; ng < 4; ++ng) {
                    uint32_t boff = ((b_row + ng * 16) * S2 + k0 + b_k) * 2;
                    uint32_t bh[4];
                    ldsm4(sb + SM_B2H + boff, bh);
                    #pragma unroll
                    for (int nj = 0; nj < 2; ++nj) {
                        mma16816(c[0][ng * 2 + nj], ah0, bh[2*nj], bh[2*nj+1]);
                        mma16816(c[1][ng * 2 + nj], ah1, bh[2*nj], bh[2*nj+1]);
                    }
                }
            }
            // partner-half k-tiles (k cols nb0^64 ..): A via ldsm from H
            const uint32_t a_row = m0 + (lane & 15);
            const uint32_t a_k   = (lane >> 4) << 3;
            const int pb = nb0 ^ 64;
            #pragma unroll
            for (int kl = 0; kl < 4; ++kl) {
                const uint32_t k0 = pb + kl * 16;
                uint32_t ah[2][4];
                #pragma unroll
                for (int mi = 0; mi < 2; ++mi) {
                    uint32_t off = ((a_row + mi * 16) * S2 + k0 + a_k) * 2;
                    ldsm4(sb + SM_HH + off, ah[mi]);
                }
                #pragma unroll
                for (int ng = 0; ng < 4; ++ng) {
                    uint32_t boff = ((b_row + ng * 16) * S2 + k0 + b_k) * 2;
                    uint32_t bh[4];
                    ldsm4(sb + SM_B2H + boff, bh);
                    #pragma unroll
                    for (int mi = 0; mi < 2; ++mi)
                        #pragma unroll
                        for (int nj = 0; nj < 2; ++nj)
                            mma16816(c[mi][ng * 2 + nj], ah[mi],
                                     bh[2*nj], bh[2*nj+1]);
                }
            }
        }
        bar_pair(bid);   // #2: pair GEMM2 done (H free) + A(next) staged

        // ---- epilogue: x(fp16 image)*(D2+b2), shfl.xor reduce over nb ----
        {
            const int j0 = __shfl_sync(0xffffffffu, j, qr);
            const int j1 = __shfl_sync(0xffffffffu, j, qr + 8);
            const int j2 = __shfl_sync(0xffffffffu, j, qr + 16);
            const int j3 = __shfl_sync(0xffffffffu, j, qr + 24);
            const __half* xr0 = g_ximg + (size_t)j0 * F_DIM;
            const __half* xr1 = g_ximg + (size_t)j1 * F_DIM;
            const __half* xr2 = g_ximg + (size_t)j2 * F_DIM;
            const __half* xr3 = g_ximg + (size_t)j3 * F_DIM;
            float* orow = out + (size_t)atom * F_DIM;
            #pragma unroll
            for (int ng = 0; ng < 8; ++ng) {
                const int cc = nb0 + ng * 8 + qc;
                const float2 bv  = *(const float2*)&bs2[cc];
                const float2 x0v = __half22float2(*(const __half2*)(xr0 + cc));
                const float2 x1v = __half22float2(*(const __half2*)(xr1 + cc));
                const float2 x2v = __half22float2(*(const __half2*)(xr2 + cc));
                const float2 x3v = __half22float2(*(const __half2*)(xr3 + cc));
                float s0 = (c[0][ng][0] + bv.x) * x0v.x
                         + (c[0][ng][2] + bv.x) * x1v.x
                         + (c[1][ng][0] + bv.x) * x2v.x
                         + (c[1][ng][2] + bv.x) * x3v.x;
                float s1 = (c[0][ng][1] + bv.y) * x0v.y
                         + (c[0][ng][3] + bv.y) * x1v.y
                         + (c[1][ng][1] + bv.y) * x2v.y
                         + (c[1][ng][3] + bv.y) * x3v.y;
                s0 += __shfl_xor_sync(0xffffffffu, s0, 4);
                s1 += __shfl_xor_sync(0xffffffffu, s1, 4);
                s0 += __shfl_xor_sync(0xffffffffu, s0, 8);
                s1 += __shfl_xor_sync(0xffffffffu, s1, 8);
                s0 += __shfl_xor_sync(0xffffffffu, s0, 16);
                s1 += __shfl_xor_sync(0xffffffffu, s1, 16);
                if (ok && qr == 0)
                    *(float2*)(orow + cc) = make_float2(s0, s1);
            }
        }
        // no bar#3: epilogue touches no shared scratch.
    }
}

// ---------------------------------------------------------------------------
extern "C" void kernel_launch(void* const* d_in, const int* in_sizes, int n_in,
                              void* d_out, int out_size)
{
    const float* x    = (const float*)d_in[0];
    const float* rbf  = (const float*)d_in[1];
    const void*  nbrs = d_in[2];
    const float* w1   = (const float*)d_in[3];
    const float* b1   = (const float*)d_in[4];
    const float* w2   = (const float*)d_in[5];
    const float* b2   = (const float*)d_in[6];
    float* out = (float*)d_out;

    const int n_atoms = in_sizes[0] / F_DIM;

    cudaFuncSetAttribute(cfconv_mma,
                         cudaFuncAttributeMaxDynamicSharedMemorySize, SMEM_BYTES);

    prep_weights<<<256, 256>>>(w1, w2, x, in_sizes[0], (const int*)nbrs);

    const int grid = (n_atoms + ATOMS_PER_CTA - 1) / ATOMS_PER_CTA;
    cfconv_mma<<<grid, N_THREADS, SMEM_BYTES>>>(x, rbf, nbrs, b1, b2, out, n_atoms);
}

// round 16
// speedup vs baseline: 1.1738x; 1.1738x over previous
#include <cuda_runtime.h>
#include <cuda_fp16.h>
#include <cstdint>

// ===========================================================================
// CFConv via mma.sync (HMMA fp16 m16n8k16, fp32 accum), single-pass fp16.
// 256 thr / CTA = 8 warps = 4 atom-PAIRS (2 warps per atom, N=64 per warp).
// R16 = R13 epilogue (fp16 wb in atom's dead H rows + L1-cached fp32 x gather)
//     + R14 GEMM2 (own-half A2 frags forwarded from softplus registers)
//     + 16 atoms/CTA (2x weight-copy amortization), early j load.
// 3 named barriers per tile; next-tile A staged under GEMM2.
// ===========================================================================

#define N_THREADS 256
#define ATOMS_PER_CTA 16
#define F_DIM 128

// padded element strides (odd multiples of 8 halves -> conflict-free ldmatrix)
#define S1 72    // K=64 tiles
#define S2 136   // K=128 tiles

// ---- smem byte offsets ----
#define SM_B1H 0                         // 128*72*2  = 18432
#define SM_B2H (SM_B1H + 128*S1*2)       // 128*136*2 = 34816 -> ends 53248
#define SM_A1H (SM_B2H + 128*S2*2)       // 128*72*2  = 18432 -> ends 71680
#define SM_HH  (SM_A1H + 128*S1*2)       // 128*136*2 = 34816 -> ends 106496
#define SM_BS1 (SM_HH  + 128*S2*2)       // 512
#define SM_BS2 (SM_BS1 + 512)
#define SMEM_BYTES (SM_BS2 + 512)        // 107520 (2 CTAs: 215040 <= 227328)

#define WIMG_BYTES (128*S1*2 + 128*S2*2) // 53248
__device__ __align__(16) unsigned char g_wimg[WIMG_BYTES];
__device__ int g_idx64_flag;

// ---------------------------------------------------------------------------
__device__ __forceinline__ uint32_t smem_u32(const void* p) {
    uint32_t a;
    asm("{ .reg .u64 t; cvta.to.shared.u64 t, %1; cvt.u32.u64 %0, t; }" : "=r"(a) : "l"(p));
    return a;
}
__device__ __forceinline__ void bar_pair(int id) {
    asm volatile("bar.sync %0, %1;" :: "r"(id), "r"(64) : "memory");
}
__device__ __forceinline__ void ldsm4(uint32_t addr, uint32_t r[4]) {
    asm volatile("ldmatrix.sync.aligned.m8n8.x4.shared.b16 {%0,%1,%2,%3}, [%4];"
        : "=r"(r[0]), "=r"(r[1]), "=r"(r[2]), "=r"(r[3]) : "r"(addr));
}
__device__ __forceinline__ void mma16816(float c[4], const uint32_t a[4],
                                         uint32_t b0, uint32_t b1) {
    asm volatile("mma.sync.aligned.m16n8k16.row.col.f32.f16.f16.f32 "
        "{%0,%1,%2,%3}, {%4,%5,%6,%7}, {%8,%9}, {%0,%1,%2,%3};"
        : "+f"(c[0]), "+f"(c[1]), "+f"(c[2]), "+f"(c[3])
        : "r"(a[0]), "r"(a[1]), "r"(a[2]), "r"(a[3]), "r"(b0), "r"(b1));
}
__device__ __forceinline__ float softplus_fast(float z) {
    return fmaxf(z, 0.0f) + __logf(1.0f + __expf(-fabsf(z)));
}
__device__ __forceinline__ uint32_t pack_h2(float a, float b) {
    __half2 h = __floats2half2_rn(a, b);
    return *reinterpret_cast<uint32_t*>(&h);
}

// A: [128 rows][STRIDE k] fp16; B: [128 n][STRIDE k] fp16. Single pass.
template<int KSTEPS, int STRIDE>
__device__ __forceinline__ void gemm_block(
    uint32_t aH, uint32_t bH,
    int m0, int nb0, int lane, float c[2][8][4])
{
    const uint32_t a_row = m0 + (lane & 15);
    const uint32_t a_k   = (lane >> 4) << 3;
    const uint32_t b_row = nb0 + ((lane >> 4) << 3) + (lane & 7);
    const uint32_t b_k   = ((lane >> 3) & 1) << 3;
    #pragma unroll
    for (int ks = 0; ks < KSTEPS; ++ks) {
        const uint32_t k0 = ks * 16;
        uint32_t ah[2][4];
        #pragma unroll
        for (int mi = 0; mi < 2; ++mi) {
            uint32_t off = ((a_row + mi * 16) * STRIDE + k0 + a_k) * 2;
            ldsm4(aH + off, ah[mi]);
        }
        #pragma unroll
        for (int ng = 0; ng < 4; ++ng) {
            uint32_t boff = ((b_row + ng * 16) * STRIDE + k0 + b_k) * 2;
            uint32_t bh[4];
            ldsm4(bH + boff, bh);
            #pragma unroll
            for (int mi = 0; mi < 2; ++mi)
                #pragma unroll
                for (int nj = 0; nj < 2; ++nj)
                    mma16816(c[mi][ng * 2 + nj], ah[mi], bh[2*nj], bh[2*nj+1]);
        }
    }
}

// stage one atom's rbf rows [32 x 64] -> fp16 into A (pair-cooperative, 64 thr)
__device__ __forceinline__ void stage_A(char* smem, const float* __restrict__ rbf,
                                        int atom, bool ok, int m0, int pt)
{
    const float4* rg = (const float4*)rbf + (size_t)atom * 512;
    #pragma unroll
    for (int i = 0; i < 8; ++i) {
        int idx = pt + i * 64;                 // 0..511
        int row = idx >> 4, c4 = (idx & 15) << 2;
        float4 v = make_float4(0.f, 0.f, 0.f, 0.f);
        if (ok) v = rg[idx];
        uint32_t o = (uint32_t)((m0 + row) * S1 + c4) * 2;
        *(uint2*)(smem + SM_A1H + o) =
            make_uint2(pack_h2(v.x, v.y), pack_h2(v.z, v.w));
    }
}

// ---------------------------------------------------------------------------
// prep: weight transpose + fp16 images; block 0 detects neighbors dtype
// ---------------------------------------------------------------------------
__global__ void prep_weights(const float* __restrict__ w1,
                             const float* __restrict__ w2,
                             const int*   __restrict__ nb_raw) {
    if (blockIdx.x == 0) {
        __shared__ int nonzero;
        if (threadIdx.x == 0) nonzero = 0;
        __syncthreads();
        int local = 0;
        for (int i = threadIdx.x; i < 1024; i += blockDim.x) local |= nb_raw[2 * i + 1];
        if (local) atomicOr(&nonzero, 1);
        __syncthreads();
        if (threadIdx.x == 0) g_idx64_flag = (nonzero == 0) ? 1 : 0;
    }
    uint16_t* b1h = (uint16_t*)(g_wimg);
    uint16_t* b2h = (uint16_t*)(g_wimg + 128*S1*2);
    int stride = gridDim.x * blockDim.x;
    int g0 = blockIdx.x * blockDim.x + threadIdx.x;
    for (int idx = g0; idx < 64*128; idx += stride) {
        int r = idx >> 7, f = idx & 127;
        b1h[f * S1 + r] = __half_as_ushort(__float2half_rn(w1[idx]));
    }
    for (int idx = g0; idx < 128*128; idx += stride) {
        int g = idx >> 7, f = idx & 127;
        b2h[f * S2 + g] = __half_as_ushort(__float2half_rn(w2[idx]));
    }
}

// ---------------------------------------------------------------------------
__global__ __launch_bounds__(N_THREADS, 2)
void cfconv_mma(const float* __restrict__ x,
                const float* __restrict__ rbf,
                const void*  __restrict__ nbr,
                const float* __restrict__ b1,
                const float* __restrict__ b2,
                float* __restrict__ out,
                int n_atoms)
{
    extern __shared__ __align__(16) char smem[];
    const uint32_t sb = smem_u32(smem);
    const int t = threadIdx.x, wid = t >> 5, lane = t & 31;

    // weights image -> smem: 53248 B = 3328 float4 = 13 x 256
    {
        const float4* src = (const float4*)g_wimg;
        float4* dst = (float4*)smem;
        #pragma unroll
        for (int i = 0; i < 13; ++i) dst[t + i * N_THREADS] = src[t + i * N_THREADS];
    }
    if (t < F_DIM) {
        ((float*)(smem + SM_BS1))[t] = b1[t];
        ((float*)(smem + SM_BS2))[t] = b2[t];
    }

    const int idxsh = g_idx64_flag;
    const int* nb32 = (const int*)nbr;
    const float* bs1 = (const float*)(smem + SM_BS1);
    const float* bs2 = (const float*)(smem + SM_BS2);

    // pair = consecutive warps {2p, 2p+1}; 4 pairs cover all SMSPs.
    const int pr  = wid >> 1;           // atom slot within tile (0..3)
    const int sub = wid & 1;            // N-half (0..1)
    const int bid = pr + 1;             // named barrier id (1..4), 64 thr
    const int m0  = pr * 32;
    const int nb0 = sub * 64;
    const int pt  = sub * 32 + lane;    // thread index within pair (0..63)
    const int qr  = lane >> 2;
    const int qc  = (lane & 3) * 2;

    __syncthreads();   // weights/biases ready (only CTA-wide sync)

    // ---- prologue: stage tile 0's A rows ----
    {
        const int atom0 = blockIdx.x * ATOMS_PER_CTA + pr;
        stage_A(smem, rbf, atom0, atom0 < n_atoms, m0, pt);
    }
    bar_pair(bid);       // A(0) ready

    #pragma unroll 1
    for (int tile = 0; tile < ATOMS_PER_CTA / 4; ++tile) {
        const int abase = blockIdx.x * ATOMS_PER_CTA + tile * 4;
        const int atom  = abase + pr;
        const bool ok   = (atom < n_atoms);

        // neighbor indices: hoisted to tile top (hides behind both GEMMs)
        int j = 0;
        if (ok) j = nb32[((size_t)atom * 32 + lane) << idxsh];

        float c[2][8][4];
        #pragma unroll
        for (int mi = 0; mi < 2; ++mi)
            #pragma unroll
            for (int ng = 0; ng < 8; ++ng)
                c[mi][ng][0] = c[mi][ng][1] = c[mi][ng][2] = c[mi][ng][3] = 0.f;

        // ---- GEMM1: A@B1 (fp16) ----
        gemm_block<4, S1>(sb + SM_A1H, sb + SM_B1H, m0, nb0, lane, c);

        // ---- softplus(D1+b1): packs -> regs (A2 own-half frags) + smem ----
        uint32_t hA[2][8], hB[2][8];   // row qr / row qr+8 packs
        #pragma unroll
        for (int mi = 0; mi < 2; ++mi) {
            #pragma unroll
            for (int ng = 0; ng < 8; ++ng) {
                const int cc = nb0 + ng * 8 + qc;
                const int r0 = m0 + mi * 16 + qr;
                float s0 = softplus_fast(c[mi][ng][0] + bs1[cc]);
                float s1 = softplus_fast(c[mi][ng][1] + bs1[cc + 1]);
                float s2 = softplus_fast(c[mi][ng][2] + bs1[cc]);
                float s3 = softplus_fast(c[mi][ng][3] + bs1[cc + 1]);
                hA[mi][ng] = pack_h2(s0, s1);
                hB[mi][ng] = pack_h2(s2, s3);
                *(uint32_t*)(smem + SM_HH + (uint32_t)(r0 * S2 + cc) * 2)
                    = hA[mi][ng];
                *(uint32_t*)(smem + SM_HH + (uint32_t)((r0 + 8) * S2 + cc) * 2)
                    = hB[mi][ng];
            }
        }
        bar_pair(bid);   // #1: H halves ready; A consumed by pair's GEMM1

        // ---- stage NEXT tile's A under GEMM2 latency ----
        if (tile + 1 < ATOMS_PER_CTA / 4) {
            const int natom = abase + 4 + pr;
            stage_A(smem, rbf, natom, natom < n_atoms, m0, pt);
        }

        #pragma unroll
        for (int mi = 0; mi < 2; ++mi)
            #pragma unroll
            for (int ng = 0; ng < 8; ++ng)
                c[mi][ng][0] = c[mi][ng][1] = c[mi][ng][2] = c[mi][ng][3] = 0.f;

        // ---- GEMM2: H@B2 (fp16). Own 4 k-tiles from regs, partner 4 via ldsm.
        {
            const uint32_t b_row = nb0 + ((lane >> 4) << 3) + (lane & 7);
            const uint32_t b_k   = ((lane >> 3) & 1) << 3;
            // own-half k-tiles (k cols nb0..nb0+63): A frags = softplus packs
            #pragma unroll
            for (int kl = 0; kl < 4; ++kl) {
                uint32_t ah0[4] = { hA[0][2*kl], hB[0][2*kl],
                                    hA[0][2*kl+1], hB[0][2*kl+1] };
                uint32_t ah1[4] = { hA[1][2*kl], hB[1][2*kl],
                                    hA[1][2*kl+1], hB[1][2*kl+1] };
                const uint32_t k0 = nb0 + kl * 16;
                #pragma unroll
                for (int ng = 0; ng < 4; ++ng) {
                    uint32_t boff = ((b_row + ng * 16) * S2 + k0 + b_k) * 2;
                    uint32_t bh[4];
                    ldsm4(sb + SM_B2H + boff, bh);
                    #pragma unroll
                    for (int nj = 0; nj < 2; ++nj) {
                        mma16816(c[0][ng * 2 + nj], ah0, bh[2*nj], bh[2*nj+1]);
                        mma16816(c[1][ng * 2 + nj], ah1, bh[2*nj], bh[2*nj+1]);
                    }
                }
            }
            // partner-half k-tiles (k cols nb0^64 ..): A via ldsm from H
            const uint32_t a_row = m0 + (lane & 15);
            const uint32_t a_k   = (lane >> 4) << 3;
            const int pb = nb0 ^ 64;
            #pragma unroll
            for (int kl = 0; kl < 4; ++kl) {
                const uint32_t k0 = pb + kl * 16;
                uint32_t ah[2][4];
                #pragma unroll
                for (int mi = 0; mi < 2; ++mi) {
                    uint32_t off = ((a_row + mi * 16) * S2 + k0 + a_k) * 2;
                    ldsm4(sb + SM_HH + off, ah[mi]);
                }
                #pragma unroll
                for (int ng = 0; ng < 4; ++ng) {
                    uint32_t boff = ((b_row + ng * 16) * S2 + k0 + b_k) * 2;
                    uint32_t bh[4];
                    ldsm4(sb + SM_B2H + boff, bh);
                    #pragma unroll
                    for (int mi = 0; mi < 2; ++mi)
                        #pragma unroll
                        for (int nj = 0; nj < 2; ++nj)
                            mma16816(c[mi][ng * 2 + nj], ah[mi],
                                     bh[2*nj], bh[2*nj+1]);
                }
            }
        }
        bar_pair(bid);   // #2: pair GEMM2 done (H rows free) + A(next) staged

        // ---- epilogue (R13): wb = half(D2+b2) in atom's dead H rows; gather --
        {
            // atom's H rows = 8704 B; per-warp fp16 scratch 32x68 halves=4352 B
            uint32_t* wb = (uint32_t*)(smem + SM_HH + (uint32_t)m0 * S2 * 2
                                       + (uint32_t)sub * 4352);
            #pragma unroll
            for (int mi = 0; mi < 2; ++mi) {
                #pragma unroll
                for (int ng = 0; ng < 8; ++ng) {
                    const int cc = nb0 + ng * 8 + qc;     // global col
                    const int lw = ng * 4 + (lane & 3);   // half2 slot 0..31
                    const int r0 = mi * 16 + qr;          // local nb row
                    wb[r0 * 34 + lw] =
                        pack_h2(c[mi][ng][0] + bs2[cc], c[mi][ng][1] + bs2[cc + 1]);
                    wb[(r0 + 8) * 34 + lw] =
                        pack_h2(c[mi][ng][2] + bs2[cc], c[mi][ng][3] + bs2[cc + 1]);
                }
            }
            __syncwarp();

            const __half* wbh = (const __half*)wb;
            const float* x0 = x + nb0 + lane;
            float a0 = 0.f, a1 = 0.f, a2 = 0.f, a3 = 0.f;
            #pragma unroll
            for (int nb = 0; nb < 32; nb += 2) {
                const int j0 = __shfl_sync(0xffffffffu, j, nb);
                const int j1 = __shfl_sync(0xffffffffu, j, nb + 1);
                const float* r0p = x0 + (size_t)j0 * F_DIM;
                const float* r1p = x0 + (size_t)j1 * F_DIM;
                a0 = fmaf(__ldg(r0p),      __half2float(wbh[nb * 68 + lane]), a0);
                a1 = fmaf(__ldg(r0p + 32), __half2float(wbh[nb * 68 + 32 + lane]), a1);
                a2 = fmaf(__ldg(r1p),      __half2float(wbh[(nb+1) * 68 + lane]), a2);
                a3 = fmaf(__ldg(r1p + 32), __half2float(wbh[(nb+1) * 68 + 32 + lane]), a3);
            }
            if (ok) {
                out[(size_t)atom * F_DIM + nb0 + lane]      = a0 + a2;
                out[(size_t)atom * F_DIM + nb0 + 32 + lane] = a1 + a3;
            }
        }
        bar_pair(bid);   // #3: both epilogues done -> H rows safe for next
                         //     tile's softplus writes (wb lives in H rows)
    }
}

// ---------------------------------------------------------------------------
extern "C" void kernel_launch(void* const* d_in, const int* in_sizes, int n_in,
                              void* d_out, int out_size)
{
    const float* x    = (const float*)d_in[0];
    const float* rbf  = (const float*)d_in[1];
    const void*  nbrs = d_in[2];
    const float* w1   = (const float*)d_in[3];
    const float* b1   = (const float*)d_in[4];
    const float* w2   = (const float*)d_in[5];
    const float* b2   = (const float*)d_in[6];
    float* out = (float*)d_out;

    const int n_atoms = in_sizes[0] / F_DIM;

    cudaFuncSetAttribute(cfconv_mma,
                         cudaFuncAttributeMaxDynamicSharedMemorySize, SMEM_BYTES);

    prep_weights<<<64, 256>>>(w1, w2, (const int*)nbrs);

    const int grid = (n_atoms + ATOMS_PER_CTA - 1) / ATOMS_PER_CTA;
    cfconv_mma<<<grid, N_THREADS, SMEM_BYTES>>>(x, rbf, nbrs, b1, b2, out, n_atoms);
}